// round 3
// baseline (speedup 1.0000x reference)
#include <cuda_runtime.h>

#define Bn 256
#define Sn 196
#define Dn 2048
#define Hn 512
#define KSPLIT 8
#define KCHUNK (Dn / KSPLIT)   // 256

// Scratch (no cudaMalloc allowed)
__device__ float g_atth_part[KSPLIT * Bn * Hn];  // 4 MB split-K partials

// tanh via 1 - 2/(e^{2x}+1): one MUFU.EX2 + one MUFU.RCP, abs err ~1e-6.
__device__ __forceinline__ float fast_tanh(float x) {
    float t = __expf(2.0f * x);
    return 1.0f - 2.0f / (t + 1.0f);
}

// ---------------------------------------------------------------------------
// Kernel 1: split-K GEMM partials.
//   part[z][m][n] = sum_{k in chunk z} h[m,k] * W[n,k]
// M=256, N=512, K-chunk=256. 32x32 tile, 128 threads, 4x2/thread.
// Grid (16, 8, 8) = 1024 blocks.
// ---------------------------------------------------------------------------
__global__ __launch_bounds__(128) void k_h2att_sk(const float* __restrict__ A,
                                                  const float* __restrict__ W) {
    __shared__ float As[32 * 36];  // [k][m], pad 36 keeps float4 alignment
    __shared__ float Bs[32 * 34];  // [k][n], pad 34 keeps float2 alignment
    const int tid = threadIdx.x;
    const int tx = tid & 15;   // n group (2 cols)
    const int ty = tid >> 4;   // m group (4 rows)
    const int m0 = blockIdx.y * 32;
    const int n0 = blockIdx.x * 32;
    const int kbase = blockIdx.z * KCHUNK;

    float acc[4][2] = {};

    for (int kt = 0; kt < KCHUNK; kt += 32) {
        const int k0 = kbase + kt;
#pragma unroll
        for (int i = 0; i < 8; i++) {
            int idx = i * 128 + tid;
            int r = idx >> 5;
            int c = idx & 31;
            As[c * 36 + r] = A[(m0 + r) * Dn + k0 + c];
            Bs[c * 34 + r] = W[(n0 + r) * Dn + k0 + c];
        }
        __syncthreads();
#pragma unroll
        for (int k = 0; k < 32; k++) {
            float4 a = *(const float4*)&As[k * 36 + ty * 4];
            float2 b = *(const float2*)&Bs[k * 34 + tx * 2];
            acc[0][0] += a.x * b.x; acc[0][1] += a.x * b.y;
            acc[1][0] += a.y * b.x; acc[1][1] += a.y * b.y;
            acc[2][0] += a.z * b.x; acc[2][1] += a.z * b.y;
            acc[3][0] += a.w * b.x; acc[3][1] += a.w * b.y;
        }
        __syncthreads();
    }

    float* dst = g_atth_part + (size_t)blockIdx.z * (Bn * Hn);
#pragma unroll
    for (int i = 0; i < 4; i++)
#pragma unroll
        for (int j = 0; j < 2; j++)
            dst[(m0 + ty * 4 + i) * Hn + n0 + tx * 2 + j] = acc[i][j];
}

// ---------------------------------------------------------------------------
// Kernel 2: FUSED scores + masked softmax + weighted sum. One block per batch,
// 512 threads (16 warps). Phases pipeline across SMs so p_att traffic and
// att_feats traffic overlap on the DRAM bus.
//
// Softmax simplification: the unmasked normalizer cancels:
//   w_i = e_i*m_i / sum_j(e_j*m_j),  e_i = exp(sc_i - max)
// so only TWO block reductions (max, sum) are needed.
// ---------------------------------------------------------------------------
__global__ __launch_bounds__(512) void k_fused(const float* __restrict__ p_att,
                                               const float* __restrict__ w_alpha,
                                               const float* __restrict__ bias,
                                               const float* __restrict__ b_alpha,
                                               const float* __restrict__ mask,
                                               const float* __restrict__ att_feats,
                                               float* __restrict__ out) {
    __shared__ float ah[Hn];
    __shared__ float wa[Hn];
    __shared__ float sc[Sn];
    __shared__ float red[16];

    const int b = blockIdx.x;
    const int tid = threadIdx.x;
    const int lane = tid & 31;
    const int warp = tid >> 5;

    // ---- assemble att_h[b] from split-K partials (+bias); stage w_alpha ----
    {
        float acc = bias[tid];
#pragma unroll
        for (int z = 0; z < KSPLIT; z++)
            acc += g_atth_part[z * (Bn * Hn) + b * Hn + tid];
        ah[tid] = acc;
        wa[tid] = w_alpha[tid];
    }
    __syncthreads();

    const float balpha = b_alpha[0];
    const float4* a4p = (const float4*)ah;
    const float4* w4p = (const float4*)wa;

    // ---- phase 1: scores, warp per s-slot ----
    for (int s = warp; s < Sn; s += 16) {
        const float4* pr = (const float4*)(p_att + ((long)b * Sn + s) * Hn);
        float local = 0.0f;
#pragma unroll
        for (int i = 0; i < 4; i++) {
            int h4 = i * 32 + lane;        // 0..127 float4 slots
            float4 p4 = pr[h4];
            float4 a4 = a4p[h4];
            float4 w4 = w4p[h4];
            local += fast_tanh(p4.x + a4.x) * w4.x;
            local += fast_tanh(p4.y + a4.y) * w4.y;
            local += fast_tanh(p4.z + a4.z) * w4.z;
            local += fast_tanh(p4.w + a4.w) * w4.w;
        }
#pragma unroll
        for (int o = 16; o > 0; o >>= 1)
            local += __shfl_xor_sync(0xffffffffu, local, o);
        if (lane == 0) sc[s] = local + balpha;
    }
    __syncthreads();

    // ---- phase 2: masked softmax (max + single sum; first norm cancels) ----
    float v = (tid < Sn) ? sc[tid] : -3.402823e38f;
    float m = v;
#pragma unroll
    for (int o = 16; o > 0; o >>= 1)
        m = fmaxf(m, __shfl_xor_sync(0xffffffffu, m, o));
    if (lane == 0) red[warp] = m;
    __syncthreads();
    if (warp == 0) {
        float t = (lane < 16) ? red[lane] : -3.402823e38f;
#pragma unroll
        for (int o = 8; o > 0; o >>= 1)
            t = fmaxf(t, __shfl_xor_sync(0xffffffffu, t, o));
        if (lane == 0) red[0] = t;
    }
    __syncthreads();
    m = red[0];
    __syncthreads();

    float em = (tid < Sn) ? __expf(v - m) * mask[b * Sn + tid] : 0.0f;
    float s1 = em;
#pragma unroll
    for (int o = 16; o > 0; o >>= 1)
        s1 += __shfl_xor_sync(0xffffffffu, s1, o);
    if (lane == 0) red[warp] = s1;
    __syncthreads();
    if (warp == 0) {
        float t = (lane < 16) ? red[lane] : 0.0f;
#pragma unroll
        for (int o = 8; o > 0; o >>= 1)
            t += __shfl_xor_sync(0xffffffffu, t, o);
        if (lane == 0) red[0] = t;
    }
    __syncthreads();
    const float inv = 1.0f / red[0];
    if (tid < Sn) sc[tid] = em * inv;   // reuse sc[] as weights
    __syncthreads();

    // ---- phase 3: att_res[b, tid*4 .. +3] = sum_s w[s] * att_feats[b,s,:] ----
    const float* base = att_feats + (long)b * Sn * Dn + tid * 4;
    float4 acc = make_float4(0.f, 0.f, 0.f, 0.f);
#pragma unroll 8
    for (int s = 0; s < Sn; s++) {
        float4 f = *(const float4*)(base + (long)s * Dn);
        float ws = sc[s];
        acc.x += ws * f.x;
        acc.y += ws * f.y;
        acc.z += ws * f.z;
        acc.w += ws * f.w;
    }
    *(float4*)(out + (long)b * Dn + tid * 4) = acc;
}

// ---------------------------------------------------------------------------

extern "C" void kernel_launch(void* const* d_in, const int* in_sizes, int n_in,
                              void* d_out, int out_size) {
    const float* h         = (const float*)d_in[0];  // [B, D]
    const float* att_feats = (const float*)d_in[1];  // [B, S, D]
    const float* p_att     = (const float*)d_in[2];  // [B, S, H]
    const float* mask      = (const float*)d_in[3];  // [B, S]
    const float* W_h2att   = (const float*)d_in[4];  // [H, D]
    const float* b_h2att   = (const float*)d_in[5];  // [H]
    const float* w_alpha   = (const float*)d_in[6];  // [H]
    const float* b_alpha   = (const float*)d_in[7];  // scalar
    float* out = (float*)d_out;                      // [B, D]

    (void)in_sizes; (void)n_in; (void)out_size;

    dim3 g1(Hn / 32, Bn / 32, KSPLIT);  // (16, 8, 8) = 1024 blocks
    k_h2att_sk<<<g1, 128>>>(h, W_h2att);

    k_fused<<<Bn, 512>>>(p_att, w_alpha, b_h2att, b_alpha, mask, att_feats, out);
}

// round 4
// speedup vs baseline: 1.3399x; 1.3399x over previous
#include <cuda_runtime.h>

#define Bn 256
#define Sn 196
#define Dn 2048
#define Hn 512
#define KSPLIT 8
#define KCHUNK (Dn / KSPLIT)   // 256

// Scratch (no cudaMalloc allowed)
__device__ float g_atth_part[KSPLIT * Bn * Hn];  // 4 MB split-K partials
__device__ float g_scores[Bn * Sn];

// tanh via 1 - 2/(e^{2x}+1): one MUFU.EX2 + one MUFU.RCP, abs err ~1e-6.
__device__ __forceinline__ float fast_tanh(float x) {
    float t = __expf(2.0f * x);
    return 1.0f - 2.0f / (t + 1.0f);
}

// ---------------------------------------------------------------------------
// Kernel 1: split-K GEMM partials.
//   part[z][m][n] = sum_{k in chunk z} h[m,k] * W[n,k]
// M=256, N=512, K-chunk=256. 32x32 tile, 128 threads, 4x2/thread.
// Grid (16, 8, 8) = 1024 blocks.
// ---------------------------------------------------------------------------
__global__ __launch_bounds__(128) void k_h2att_sk(const float* __restrict__ A,
                                                  const float* __restrict__ W) {
    __shared__ float As[32 * 36];  // [k][m], pad 36 keeps float4 alignment
    __shared__ float Bs[32 * 34];  // [k][n], pad 34 keeps float2 alignment
    const int tid = threadIdx.x;
    const int tx = tid & 15;   // n group (2 cols)
    const int ty = tid >> 4;   // m group (4 rows)
    const int m0 = blockIdx.y * 32;
    const int n0 = blockIdx.x * 32;
    const int kbase = blockIdx.z * KCHUNK;

    float acc[4][2] = {};

    for (int kt = 0; kt < KCHUNK; kt += 32) {
        const int k0 = kbase + kt;
#pragma unroll
        for (int i = 0; i < 8; i++) {
            int idx = i * 128 + tid;
            int r = idx >> 5;
            int c = idx & 31;
            As[c * 36 + r] = A[(m0 + r) * Dn + k0 + c];
            Bs[c * 34 + r] = W[(n0 + r) * Dn + k0 + c];
        }
        __syncthreads();
#pragma unroll
        for (int k = 0; k < 32; k++) {
            float4 a = *(const float4*)&As[k * 36 + ty * 4];
            float2 b = *(const float2*)&Bs[k * 34 + tx * 2];
            acc[0][0] += a.x * b.x; acc[0][1] += a.x * b.y;
            acc[1][0] += a.y * b.x; acc[1][1] += a.y * b.y;
            acc[2][0] += a.z * b.x; acc[2][1] += a.z * b.y;
            acc[3][0] += a.w * b.x; acc[3][1] += a.w * b.y;
        }
        __syncthreads();
    }

    float* dst = g_atth_part + (size_t)blockIdx.z * (Bn * Hn);
#pragma unroll
    for (int i = 0; i < 4; i++)
#pragma unroll
        for (int j = 0; j < 2; j++)
            dst[(m0 + ty * 4 + i) * Hn + n0 + tx * 2 + j] = acc[i][j];
}

// ---------------------------------------------------------------------------
// Kernel 2: raw scores, 2-slot ILP. Grid (B, 7): block covers 28 s-slots.
// 448 threads = 14 warps; each warp computes TWO slots simultaneously:
// 8 independent float4 loads in flight + two independent MUFU/FMA chains.
//   scores[b,s] = sum_h tanh(p[b,s,h] + att_h[b,h]) * w_alpha[h] + b_alpha
// att_h assembled from the 8 split-K partials + bias (L2-hit loads).
// ---------------------------------------------------------------------------
__global__ __launch_bounds__(448) void k_scores(const float* __restrict__ p_att,
                                                const float* __restrict__ w_alpha,
                                                const float* __restrict__ bias,
                                                const float* __restrict__ b_alpha) {
    __shared__ float ah[Hn];
    __shared__ float wa[Hn];

    const int b = blockIdx.x;
    const int sgrp = blockIdx.y;          // 0..6, 28 slots each
    const int tid = threadIdx.x;
    const int lane = tid & 31;
    const int warp = tid >> 5;            // 0..13

    for (int h = tid; h < Hn; h += 448) {
        float acc = bias[h];
#pragma unroll
        for (int z = 0; z < KSPLIT; z++)
            acc += g_atth_part[z * (Bn * Hn) + b * Hn + h];
        ah[h] = acc;
        wa[h] = w_alpha[h];
    }
    __syncthreads();

    const float balpha = b_alpha[0];
    const float4* a4p = (const float4*)ah;
    const float4* w4p = (const float4*)wa;

    const int s0 = sgrp * 28 + warp * 2;          // this warp's slot pair
    const float4* pr0 = (const float4*)(p_att + ((long)b * Sn + s0) * Hn);
    const float4* pr1 = (const float4*)(p_att + ((long)b * Sn + s0 + 1) * Hn);

    float l0 = 0.0f, l1 = 0.0f;
#pragma unroll
    for (int i = 0; i < 4; i++) {
        const int h4 = i * 32 + lane;             // 0..127 float4 slots
        float4 pa = pr0[h4];
        float4 pb = pr1[h4];
        float4 a4 = a4p[h4];
        float4 w4 = w4p[h4];
        l0 += fast_tanh(pa.x + a4.x) * w4.x;
        l1 += fast_tanh(pb.x + a4.x) * w4.x;
        l0 += fast_tanh(pa.y + a4.y) * w4.y;
        l1 += fast_tanh(pb.y + a4.y) * w4.y;
        l0 += fast_tanh(pa.z + a4.z) * w4.z;
        l1 += fast_tanh(pb.z + a4.z) * w4.z;
        l0 += fast_tanh(pa.w + a4.w) * w4.w;
        l1 += fast_tanh(pb.w + a4.w) * w4.w;
    }
#pragma unroll
    for (int o = 16; o > 0; o >>= 1) {
        l0 += __shfl_xor_sync(0xffffffffu, l0, o);
        l1 += __shfl_xor_sync(0xffffffffu, l1, o);
    }
    if (lane == 0) {
        g_scores[b * Sn + s0]     = l0 + balpha;
        g_scores[b * Sn + s0 + 1] = l1 + balpha;
    }
}

// ---------------------------------------------------------------------------
// Kernel 3: fused masked-softmax prologue + weighted sum.
// Grid (4, B) = 1024 blocks x 128 threads. Each block redundantly computes the
// softmax from g_scores (196 L2-hit loads, ~cheap) into smem, then streams its
// 512-float slice of att_feats.
// Softmax simplification: unmasked normalizer cancels ->
//   w_i = e_i*m_i / sum_j(e_j*m_j),  e_i = exp(sc_i - max).
// ---------------------------------------------------------------------------
__global__ __launch_bounds__(128) void k_attres(const float* __restrict__ att_feats,
                                                const float* __restrict__ mask,
                                                float* __restrict__ out) {
    __shared__ float w[Sn];
    __shared__ float redm[4];
    __shared__ float reds[4];

    const int b = blockIdx.y;
    const int tid = threadIdx.x;
    const int lane = tid & 31;
    const int warp = tid >> 5;

    // ---- softmax over 196 scores (2 values/thread) ----
    const float v0 = g_scores[b * Sn + tid];                 // tid < 128 < 196
    const float v1 = (tid + 128 < Sn) ? g_scores[b * Sn + tid + 128] : -3.402823e38f;

    float m = fmaxf(v0, v1);
#pragma unroll
    for (int o = 16; o > 0; o >>= 1)
        m = fmaxf(m, __shfl_xor_sync(0xffffffffu, m, o));
    if (lane == 0) redm[warp] = m;
    __syncthreads();
    m = fmaxf(fmaxf(redm[0], redm[1]), fmaxf(redm[2], redm[3]));

    float e0 = __expf(v0 - m) * mask[b * Sn + tid];
    float e1 = (tid + 128 < Sn) ? __expf(v1 - m) * mask[b * Sn + tid + 128] : 0.0f;
    float s = e0 + e1;
#pragma unroll
    for (int o = 16; o > 0; o >>= 1)
        s += __shfl_xor_sync(0xffffffffu, s, o);
    if (lane == 0) reds[warp] = s;
    __syncthreads();
    const float inv = 1.0f / (reds[0] + reds[1] + reds[2] + reds[3]);

    w[tid] = e0 * inv;
    if (tid + 128 < Sn) w[tid + 128] = e1 * inv;
    __syncthreads();

    // ---- weighted sum: out[b, d0..d0+3] = sum_s w[s]*att_feats[b,s,d] ----
    const int d0 = blockIdx.x * 512 + tid * 4;
    const float* base = att_feats + (long)b * Sn * Dn + d0;

    float4 acc = make_float4(0.f, 0.f, 0.f, 0.f);
#pragma unroll 8
    for (int s2 = 0; s2 < Sn; s2++) {
        float4 f = *(const float4*)(base + (long)s2 * Dn);
        float ws = w[s2];
        acc.x += ws * f.x;
        acc.y += ws * f.y;
        acc.z += ws * f.z;
        acc.w += ws * f.w;
    }
    *(float4*)(out + (long)b * Dn + d0) = acc;
}

// ---------------------------------------------------------------------------

extern "C" void kernel_launch(void* const* d_in, const int* in_sizes, int n_in,
                              void* d_out, int out_size) {
    const float* h         = (const float*)d_in[0];  // [B, D]
    const float* att_feats = (const float*)d_in[1];  // [B, S, D]
    const float* p_att     = (const float*)d_in[2];  // [B, S, H]
    const float* mask      = (const float*)d_in[3];  // [B, S]
    const float* W_h2att   = (const float*)d_in[4];  // [H, D]
    const float* b_h2att   = (const float*)d_in[5];  // [H]
    const float* w_alpha   = (const float*)d_in[6];  // [H]
    const float* b_alpha   = (const float*)d_in[7];  // scalar
    float* out = (float*)d_out;                      // [B, D]

    (void)in_sizes; (void)n_in; (void)out_size;

    dim3 g1(Hn / 32, Bn / 32, KSPLIT);  // (16, 8, 8) = 1024 blocks
    k_h2att_sk<<<g1, 128>>>(h, W_h2att);

    dim3 g2(Bn, 7);                     // 1792 blocks, 448 thr
    k_scores<<<g2, 448>>>(p_att, w_alpha, b_h2att, b_alpha);

    dim3 g3(4, Bn);                     // 1024 blocks
    k_attres<<<g3, 128>>>(att_feats, mask, out);
}